// round 13
// baseline (speedup 1.0000x reference)
#include <cuda_runtime.h>
#include <cuda_bf16.h>
#include <stdint.h>
#include <math.h>

#define BATCH 128
#define HW    196
#define KC    512
#define NCLS  10
#define SFEAT (BATCH*HW*KC)   // 12845056
#define KTOT  4608            // 9 taps * 512

// ---------------- scratch (device globals; no allocation allowed) ----------
__device__ float g_x3[SFEAT];                    // relu(conv + b)
__device__ __nv_bfloat16 g_x1h[SFEAT];           // x1 split hi
__device__ __nv_bfloat16 g_x1l[SFEAT];           // x1 split lo
__device__ __nv_bfloat16 g_wth[KC*KTOT];         // W^T hi: [co][k]
__device__ __nv_bfloat16 g_wtl[KC*KTOT];         // W^T lo
__device__ float g_wtf[KC*KTOT];                 // W^T fp32 (exact resolve)
__device__ int   g_arg1[BATCH*KC];
__device__ int   g_arg2[BATCH*KC];
__device__ float g_mean1[BATCH*KC];
__device__ float g_mean2[BATCH*KC];
__device__ int   g_fcls1[KC];
__device__ int   g_fcls2[KC];
__device__ float g_logit[BATCH*2*NCLS];

__device__ __forceinline__ float tpl_val(int pi, int pj, int i, int j) {
    int di = i - pi; if (di < 0) di = -di;
    int dj = j - pj; if (dj < 0) dj = -dj;
    float v = 1.0f - (2.0f * (float)(di + dj)) / 14.0f;
    v = fmaxf(v, -1.0f);
    return (0.5f / 196.0f) * v;
}

__device__ __forceinline__ uint32_t s2u(const void* p) {
    uint32_t a;
    asm("{ .reg .u64 t; cvta.to.shared.u64 t, %1; cvt.u32.u64 %0, t; }"
        : "=r"(a) : "l"(p));
    return a;
}
__device__ __forceinline__ void ldsm4(uint32_t* r, uint32_t addr) {
    asm volatile("ldmatrix.sync.aligned.m8n8.x4.shared.b16 {%0,%1,%2,%3}, [%4];"
                 : "=r"(r[0]), "=r"(r[1]), "=r"(r[2]), "=r"(r[3]) : "r"(addr));
}
__device__ __forceinline__ void mma16816(float* d, const uint32_t* a,
                                         uint32_t b0, uint32_t b1) {
    asm volatile("mma.sync.aligned.m16n8k16.row.col.f32.bf16.bf16.f32 "
                 "{%0,%1,%2,%3}, {%4,%5,%6,%7}, {%8,%9}, {%0,%1,%2,%3};"
                 : "+f"(d[0]), "+f"(d[1]), "+f"(d[2]), "+f"(d[3])
                 : "r"(a[0]), "r"(a[1]), "r"(a[2]), "r"(a[3]), "r"(b0), "r"(b1));
}
__device__ __forceinline__ void cpasync16(uint32_t sdst, const void* gsrc, int sz) {
    asm volatile("cp.async.cg.shared.global [%0], [%1], 16, %2;"
                 :: "r"(sdst), "l"(gsrc), "r"(sz));
}
#define CP_COMMIT() asm volatile("cp.async.commit_group;" ::: "memory")
#define CP_WAIT1()  asm volatile("cp.async.wait_group 1;" ::: "memory")

// ---------------- stage 1: masked_output on inputs ---------------------------
__global__ __launch_bounds__(256) void masked1_kernel(
        const float* __restrict__ in, float* __restrict__ x1o,
        float* __restrict__ posto, float* __restrict__ rawo) {
    const int b = blockIdx.x;
    const int c = blockIdx.y * 256 + threadIdx.x;
    const size_t base = (size_t)b * HW * KC + c;
    float best = -3.402823e38f; int bi = 0;
    #pragma unroll 4
    for (int p = 0; p < HW; ++p) {
        float v = in[base + (size_t)p * KC];
        if (v > best) { best = v; bi = p; }
    }
    g_arg1[b * KC + c] = bi;
    const int pi = bi / 14, pj = bi - pi * 14;
    float s = 0.f;
    #pragma unroll 2
    for (int p = 0; p < HW; ++p) {
        const int i = p / 14, j = p - i * 14;
        const float t = tpl_val(pi, pj, i, j);
        const float v = in[base + (size_t)p * KC];
        const float m = fmaxf(v * t, 0.f);
        s += m;
        x1o[base + (size_t)p * KC]   = m;
        posto[base + (size_t)p * KC] = t;
        rawo[base + (size_t)p * KC]  = v;
    }
    g_mean1[b * KC + c] = s / 196.0f;
}

// ---------------- split x1 -> bf16 hi/lo -------------------------------------
__global__ __launch_bounds__(256) void split_x1_kernel(const float* __restrict__ x1) {
    const size_t i0 = ((size_t)blockIdx.x * 256 + threadIdx.x) * 8;
    float4 v0 = *reinterpret_cast<const float4*>(x1 + i0);
    float4 v1 = *reinterpret_cast<const float4*>(x1 + i0 + 4);
    float v[8] = {v0.x, v0.y, v0.z, v0.w, v1.x, v1.y, v1.z, v1.w};
    uint32_t ph[4], pl[4];
    #pragma unroll
    for (int j = 0; j < 4; ++j) {
        __nv_bfloat162 th, tl;
        #pragma unroll
        for (int q = 0; q < 2; ++q) {
            float x = v[2*j + q];
            __nv_bfloat16 h = __float2bfloat16(x);
            __nv_bfloat16 l = __float2bfloat16(x - __bfloat162float(h));
            if (q == 0) { th.x = h; tl.x = l; } else { th.y = h; tl.y = l; }
        }
        ph[j] = *reinterpret_cast<uint32_t*>(&th);
        pl[j] = *reinterpret_cast<uint32_t*>(&tl);
    }
    *reinterpret_cast<uint4*>(g_x1h + i0) = make_uint4(ph[0], ph[1], ph[2], ph[3]);
    *reinterpret_cast<uint4*>(g_x1l + i0) = make_uint4(pl[0], pl[1], pl[2], pl[3]);
}

// ---------------- split + transpose weights (+ fp32 copy) --------------------
__global__ __launch_bounds__(512) void split_w_kernel(const float* __restrict__ w) {
    const int k  = blockIdx.x;
    const int co = threadIdx.x;
    const float v = w[(size_t)k * KC + co];
    __nv_bfloat16 h = __float2bfloat16(v);
    __nv_bfloat16 l = __float2bfloat16(v - __bfloat162float(h));
    g_wth[(size_t)co * KTOT + k] = h;
    g_wtl[(size_t)co * KTOT + k] = l;
    g_wtf[(size_t)co * KTOT + k] = v;
}

// ---------------- stage 2: conv via mma.sync bf16 3-pass split ---------------
// Block 128x128, 128 threads = 4 warps of 64x64; cp.async double-buffered.
#define BK2     32
#define NCH     (KTOT / BK2)      // 144
#define ASTRIDE 80
#define TILEB   (128 * ASTRIDE)
#define OFF_AH  0
#define OFF_AL  (1 * TILEB)
#define OFF_BH  (2 * TILEB)
#define OFF_BL  (3 * TILEB)
#define STAGEB  (4 * TILEB)
#define SMEMC   (2 * STAGEB)      // 81920

#define CONV_LOADC(KT, S)                                                       \
    {                                                                           \
        const int kt_ = (KT);                                                   \
        const int tap = kt_ >> 4;                                               \
        const int ci0 = (kt_ & 15) << 5;                                        \
        const int kh = tap / 3, kw = tap - kh * 3;                              \
        const int ih = oh + kh - 1, iw = ow + kw - 1;                           \
        const bool av = ((unsigned)ih < 14u) && ((unsigned)iw < 14u);           \
        const int sz = av ? 16 : 0;                                             \
        const size_t ai = av ? ((((size_t)bb * HW + ih * 14 + iw) << 9) + ci0)  \
                             : 0;                                               \
        const size_t bi = bRow + ((size_t)kt_ << 5);                            \
        const uint32_t sA = smb + (S) * STAGEB + (uint32_t)tid * ASTRIDE;       \
        _Pragma("unroll")                                                       \
        for (int sg = 0; sg < 4; ++sg) {                                        \
            cpasync16(sA + OFF_AH + sg * 16, g_x1h + ai + sg * 8, sz);          \
            cpasync16(sA + OFF_AL + sg * 16, g_x1l + ai + sg * 8, sz);          \
            cpasync16(sA + OFF_BH + sg * 16, g_wth + bi + sg * 8, 16);          \
            cpasync16(sA + OFF_BL + sg * 16, g_wtl + bi + sg * 8, 16);          \
        }                                                                       \
        CP_COMMIT();                                                            \
    }

__global__ __launch_bounds__(128) void conv_mma_kernel(const float* __restrict__ bias) {
    extern __shared__ char sm[];
    const uint32_t smb = s2u(sm);
    const int tid = threadIdx.x, lane = tid & 31, wid = tid >> 5;
    const int n0 = blockIdx.x * 128;
    const int m0 = blockIdx.y * 128;
    const int wm = (wid & 1) * 64;      // 2x2 warp grid, 64x64 tiles
    const int wn = (wid >> 1) * 64;

    // loader geometry: thread t owns row t of all four tiles
    const int m  = m0 + tid;
    const int bb = m / HW;
    const int pp = m - bb * HW;
    const int oh = pp / 14, ow = pp - (pp / 14) * 14;
    const size_t bRow = (size_t)(n0 + tid) * KTOT;

    const uint32_t aAddr = smb + OFF_AH
        + (uint32_t)(wm + (lane & 15)) * ASTRIDE + ((uint32_t)(lane >> 4) << 4);
    const uint32_t bAddr = smb + OFF_BH
        + (uint32_t)(wn + ((lane >> 4) << 3) + (lane & 7)) * ASTRIDE
        + (((uint32_t)(lane >> 3) & 1u) << 4);

    float acc[4][8][4];
    #pragma unroll
    for (int i = 0; i < 4; ++i)
        #pragma unroll
        for (int j = 0; j < 8; ++j)
            #pragma unroll
            for (int q = 0; q < 4; ++q) acc[i][j][q] = 0.f;

    CONV_LOADC(0, 0);
    CONV_LOADC(1, 1);

    for (int kt = 0; kt < NCH; ++kt) {
        const int s = kt & 1;
        CP_WAIT1();
        __syncthreads();

        const uint32_t sbase = (uint32_t)(s * STAGEB);
        #pragma unroll
        for (int kk = 0; kk < 2; ++kk) {
            uint32_t ah[4][4], al[4][4];
            #pragma unroll
            for (int mi = 0; mi < 4; ++mi) {
                const uint32_t ra = aAddr + sbase + mi * (16 * ASTRIDE) + kk * 32;
                ldsm4(ah[mi], ra);
                ldsm4(al[mi], ra + (OFF_AL - OFF_AH));
            }
            #pragma unroll
            for (int np = 0; np < 4; ++np) {
                uint32_t bh[4], bl[4];
                const uint32_t rb = bAddr + sbase + np * (16 * ASTRIDE) + kk * 32;
                ldsm4(bh, rb);
                ldsm4(bl, rb + (OFF_BL - OFF_BH));
                #pragma unroll
                for (int mi = 0; mi < 4; ++mi) {
                    mma16816(acc[mi][2*np],   ah[mi], bh[0], bh[1]);
                    mma16816(acc[mi][2*np+1], ah[mi], bh[2], bh[3]);
                    mma16816(acc[mi][2*np],   ah[mi], bl[0], bl[1]);
                    mma16816(acc[mi][2*np+1], ah[mi], bl[2], bl[3]);
                    mma16816(acc[mi][2*np],   al[mi], bh[0], bh[1]);
                    mma16816(acc[mi][2*np+1], al[mi], bh[2], bh[3]);
                }
            }
        }

        __syncthreads();                         // all warps done reading stage s
        if (kt + 2 < NCH) CONV_LOADC(kt + 2, s); // refill stage s
    }

    // epilogue: bias + relu -> g_x3
    #pragma unroll
    for (int mi = 0; mi < 4; ++mi) {
        const int r0 = m0 + wm + mi * 16 + (lane >> 2);
        #pragma unroll
        for (int ni = 0; ni < 8; ++ni) {
            const int c = n0 + wn + ni * 8 + (lane & 3) * 2;
            const float2 bs = *reinterpret_cast<const float2*>(bias + c);
            float2 o0, o1;
            o0.x = fmaxf(acc[mi][ni][0] + bs.x, 0.f);
            o0.y = fmaxf(acc[mi][ni][1] + bs.y, 0.f);
            o1.x = fmaxf(acc[mi][ni][2] + bs.x, 0.f);
            o1.y = fmaxf(acc[mi][ni][3] + bs.y, 0.f);
            *reinterpret_cast<float2*>(g_x3 + ((size_t)r0 << 9) + c)       = o0;
            *reinterpret_cast<float2*>(g_x3 + ((size_t)(r0 + 8) << 9) + c) = o1;
        }
    }
}

// ---------------- exact fp32 conv output at one position (resolve path) ------
__device__ float exact_x3(const float* __restrict__ x1, float bias_c,
                          int b, int p, int c) {
    const int i = p / 14, j = p - (p / 14) * 14;
    const float* wrow = g_wtf + (size_t)c * KTOT;
    float s = 0.f;
    #pragma unroll 1
    for (int tap = 0; tap < 9; ++tap) {
        const int kh = tap / 3, kw = tap - kh * 3;
        const int ih = i + kh - 1, iw = j + kw - 1;
        if ((unsigned)ih < 14u && (unsigned)iw < 14u) {
            const float* xr = x1 + (((size_t)b * HW + ih * 14 + iw) << 9);
            const float* wr = wrow + tap * 512;
            #pragma unroll 8
            for (int ci = 0; ci < 512; ++ci) s = fmaf(xr[ci], wr[ci], s);
        }
    }
    return fmaxf(s + bias_c, 0.f);
}

// ---------------- stage 3: masked_output on x3 (robust argmax) ---------------
__global__ __launch_bounds__(256) void masked2_kernel(
        const float* __restrict__ x1, const float* __restrict__ cb,
        float* __restrict__ x2o) {
    const int b = blockIdx.x;
    const int c = blockIdx.y * 256 + threadIdx.x;
    const size_t base = (size_t)b * HW * KC + c;

    float best = -3.402823e38f; int bi = 0;
    #pragma unroll 4
    for (int p = 0; p < HW; ++p) {
        float v = g_x3[base + (size_t)p * KC];
        if (v > best) { best = v; bi = p; }
    }

    if (best > 0.f) {
        const float thresh = best - best * 5e-4f;
        int cand[8]; int nc = 0;
        for (int p = 0; p < HW; ++p) {
            float v = g_x3[base + (size_t)p * KC];
            if (v >= thresh) { if (nc < 8) cand[nc] = p; ++nc; }
        }
        if (nc > 1) {
            const float bias_c = cb[c];
            const int nn = nc < 8 ? nc : 8;
            float be = -3.402823e38f; int bidx = cand[0];
            for (int t = 0; t < nn; ++t) {
                const float e = exact_x3(x1, bias_c, b, cand[t], c);
                if (e > be) { be = e; bidx = cand[t]; }
            }
            bi = bidx;
        }
    }

    g_arg2[b * KC + c] = bi;
    const int pi = bi / 14, pj = bi - pi * 14;
    float s = 0.f;
    #pragma unroll 2
    for (int p = 0; p < HW; ++p) {
        const int i = p / 14, j = p - i * 14;
        const float t = tpl_val(pi, pj, i, j);
        const float v = g_x3[base + (size_t)p * KC];
        const float m = fmaxf(v * t, 0.f);
        s += m;
        x2o[base + (size_t)p * KC] = m;
    }
    g_mean2[b * KC + c] = s / 196.0f;
}

// ---------------- stage 4: per-channel class stats ---------------------------
__global__ __launch_bounds__(32) void stats_kernel(
        const int* __restrict__ gt,
        const float* __restrict__ as1, const float* __restrict__ cs1,
        const float* __restrict__ as2, const float* __restrict__ cs2) {
    __shared__ int s_gt[BATCH];
    const int tid = threadIdx.x;
    const int c = blockIdx.x * 32 + tid;
    const int layer = blockIdx.y;
    for (int i = tid; i < BATCH; i += 32) s_gt[i] = gt[i];
    __syncthreads();

    const float* mean = (layer == 0) ? g_mean1 : g_mean2;
    const float* as   = (layer == 0) ? as1 : as2;
    const float* cs   = (layer == 0) ? cs1 : cs2;

    float cnt[NCLS], act[NCLS];
    #pragma unroll
    for (int k = 0; k < NCLS; ++k) { cnt[k] = 0.f; act[k] = 0.f; }
    #pragma unroll 4
    for (int b = 0; b < BATCH; ++b) {
        const int   g = s_gt[b];
        const float v = mean[b * KC + c];
        #pragma unroll
        for (int k = 0; k < NCLS; ++k) {
            cnt[k] += (g == k) ? 1.0f : 0.0f;
            act[k] += (g == k) ? v    : 0.0f;
        }
    }
    int bestk = 0; float bestv = -3.402823e38f;
    #pragma unroll
    for (int k = 0; k < NCLS; ++k) {
        const float cn = cs[k] + cnt[k];
        const float fm = (cn == 0.f) ? 0.f : (as[c * NCLS + k] + act[k]) / cn;
        if (fm > bestv) { bestv = fm; bestk = k; }
    }
    if (layer == 0) g_fcls1[c] = bestk; else g_fcls2[c] = bestk;
}

// ---------------- stage 5: loss tensors --------------------------------------
__global__ __launch_bounds__(256) void loss_kernel(const int* __restrict__ gt,
                                                   float* __restrict__ l1,
                                                   float* __restrict__ l2) {
    const int bp = blockIdx.x;
    const int b = bp / HW;
    const int p = bp - b * HW;
    const int i = p / 14, j = p - (p / 14) * 14;
    const int c = blockIdx.y * 256 + threadIdx.x;
    const int gtb = gt[b];
    const size_t o = (size_t)bp * KC + c;

    float v1 = 0.f;
    if (g_fcls1[c] == gtb) {
        const int a = g_arg1[b * KC + c];
        const int pi = a / 14, pj = a - (a / 14) * 14;
        v1 = fmaxf(tpl_val(pi, pj, i, j), 0.f);
    }
    l1[o] = v1;

    float v2 = 0.f;
    if (g_fcls2[c] == gtb) {
        const int a = g_arg2[b * KC + c];
        const int pi = a / 14, pj = a - (a / 14) * 14;
        v2 = fmaxf(tpl_val(pi, pj, i, j), 0.f);
    }
    l2[o] = v2;
}

// ---------------- stage 6a: maxpool 2x2 + dense (partial) --------------------
__global__ __launch_bounds__(256) void dense_kernel(const float* __restrict__ x2,
                                                    const float* __restrict__ dw) {
    const int b    = blockIdx.x >> 1;
    const int half = blockIdx.x & 1;
    const int tid  = threadIdx.x;
    const float* xb = x2 + (size_t)b * HW * KC;
    float acc[NCLS];
    #pragma unroll
    for (int k = 0; k < NCLS; ++k) acc[k] = 0.f;

    const int D = 7 * 7 * KC;
    const int d0 = half * (D / 2);
    for (int d = d0 + tid; d < d0 + D / 2; d += 256) {
        const int c  = d & 511;
        const int pw = (d >> 9) % 7;
        const int ph = d / (KC * 7);
        const float* p00 = xb + ((size_t)((2 * ph) * 14 + 2 * pw)) * KC + c;
        const float m = fmaxf(fmaxf(p00[0], p00[KC]),
                              fmaxf(p00[14 * KC], p00[15 * KC]));
        const float* wr = dw + (size_t)d * NCLS;
        #pragma unroll
        for (int k = 0; k < NCLS; ++k) acc[k] = fmaf(m, wr[k], acc[k]);
    }

    __shared__ float sacc[NCLS];
    if (tid < NCLS) sacc[tid] = 0.f;
    __syncthreads();
    #pragma unroll
    for (int k = 0; k < NCLS; ++k) {
        float v = acc[k];
        for (int off = 16; off; off >>= 1) v += __shfl_down_sync(0xffffffffu, v, off);
        if ((tid & 31) == 0) atomicAdd(&sacc[k], v);
    }
    __syncthreads();
    if (tid < NCLS) g_logit[(b * 2 + half) * NCLS + tid] = sacc[tid];
}

// ---------------- stage 6b: combine + softmax --------------------------------
__global__ __launch_bounds__(32) void softmax_kernel(const float* __restrict__ db,
                                                     float* __restrict__ probs) {
    const int b = blockIdx.x;
    if (threadIdx.x == 0) {
        float lg[NCLS];
        float mx = -3.402823e38f;
        for (int k = 0; k < NCLS; ++k) {
            lg[k] = g_logit[(b * 2 + 0) * NCLS + k]
                  + g_logit[(b * 2 + 1) * NCLS + k] + db[k];
            mx = fmaxf(mx, lg[k]);
        }
        float s = 0.f;
        for (int k = 0; k < NCLS; ++k) { lg[k] = expf(lg[k] - mx); s += lg[k]; }
        for (int k = 0; k < NCLS; ++k) probs[b * NCLS + k] = lg[k] / s;
    }
}

// ---------------- launch ------------------------------------------------------
extern "C" void kernel_launch(void* const* d_in, const int* in_sizes, int n_in,
                              void* d_out, int out_size) {
    const float* inp     = (const float*)d_in[0];
    const int*   gt      = (const int*)  d_in[1];
    const float* conv_w  = (const float*)d_in[2];
    const float* conv_b  = (const float*)d_in[3];
    const float* dense_w = (const float*)d_in[4];
    const float* dense_b = (const float*)d_in[5];
    const float* as1     = (const float*)d_in[6];
    const float* as2     = (const float*)d_in[7];
    const float* cs1     = (const float*)d_in[8];
    const float* cs2     = (const float*)d_in[9];

    float* out   = (float*)d_out;
    float* probs = out;
    float* x1    = probs + BATCH * NCLS;
    float* x2    = x1 + SFEAT;
    float* loss1 = x2 + SFEAT;
    float* loss2 = loss1 + SFEAT;
    float* raw   = loss2 + SFEAT;
    float* post1 = raw + SFEAT;

    cudaFuncSetAttribute(conv_mma_kernel,
                         cudaFuncAttributeMaxDynamicSharedMemorySize, SMEMC);

    split_w_kernel<<<KTOT, 512>>>(conv_w);
    masked1_kernel<<<dim3(BATCH, 2), 256>>>(inp, x1, post1, raw);
    split_x1_kernel<<<SFEAT / 2048, 256>>>(x1);
    conv_mma_kernel<<<dim3(4, 196), 128, SMEMC>>>(conv_b);
    masked2_kernel<<<dim3(BATCH, 2), 256>>>(x1, conv_b, x2);
    stats_kernel<<<dim3(16, 2), 32>>>(gt, as1, cs1, as2, cs2);
    loss_kernel<<<dim3(BATCH * HW, 2), 256>>>(gt, loss1, loss2);
    dense_kernel<<<BATCH * 2, 256>>>(x2, dense_w);
    softmax_kernel<<<BATCH, 32>>>(dense_b, probs);
}

// round 14
// speedup vs baseline: 1.0902x; 1.0902x over previous
#include <cuda_runtime.h>
#include <cuda_bf16.h>
#include <stdint.h>
#include <math.h>

#define BATCH 128
#define HW    196
#define KC    512
#define NCLS  10
#define SFEAT (BATCH*HW*KC)   // 12845056
#define KTOT  4608            // 9 taps * 512

// ---------------- scratch (device globals; no allocation allowed) ----------
__device__ float g_x3[SFEAT];                    // relu(conv + b)
__device__ __nv_bfloat16 g_x1h[SFEAT];           // x1 split hi
__device__ __nv_bfloat16 g_x1l[SFEAT];           // x1 split lo
__device__ __nv_bfloat16 g_wth[KC*KTOT];         // W^T hi: [co][k]
__device__ __nv_bfloat16 g_wtl[KC*KTOT];         // W^T lo
__device__ float g_wtf[KC*KTOT];                 // W^T fp32 (exact resolve)
__device__ int   g_arg1[BATCH*KC];
__device__ int   g_arg2[BATCH*KC];
__device__ float g_mean1[BATCH*KC];
__device__ float g_mean2[BATCH*KC];
__device__ int   g_fcls1[KC];
__device__ int   g_fcls2[KC];
__device__ float g_logit[BATCH*2*NCLS];

__device__ __forceinline__ float tpl_val(int pi, int pj, int i, int j) {
    int di = i - pi; if (di < 0) di = -di;
    int dj = j - pj; if (dj < 0) dj = -dj;
    float v = 1.0f - (2.0f * (float)(di + dj)) / 14.0f;
    v = fmaxf(v, -1.0f);
    return (0.5f / 196.0f) * v;
}

__device__ __forceinline__ uint32_t s2u(const void* p) {
    uint32_t a;
    asm("{ .reg .u64 t; cvta.to.shared.u64 t, %1; cvt.u32.u64 %0, t; }"
        : "=r"(a) : "l"(p));
    return a;
}
__device__ __forceinline__ void ldsm4(uint32_t* r, uint32_t addr) {
    asm volatile("ldmatrix.sync.aligned.m8n8.x4.shared.b16 {%0,%1,%2,%3}, [%4];"
                 : "=r"(r[0]), "=r"(r[1]), "=r"(r[2]), "=r"(r[3]) : "r"(addr));
}
__device__ __forceinline__ void mma16816(float* d, const uint32_t* a,
                                         uint32_t b0, uint32_t b1) {
    asm volatile("mma.sync.aligned.m16n8k16.row.col.f32.bf16.bf16.f32 "
                 "{%0,%1,%2,%3}, {%4,%5,%6,%7}, {%8,%9}, {%0,%1,%2,%3};"
                 : "+f"(d[0]), "+f"(d[1]), "+f"(d[2]), "+f"(d[3])
                 : "r"(a[0]), "r"(a[1]), "r"(a[2]), "r"(a[3]), "r"(b0), "r"(b1));
}
__device__ __forceinline__ void cpasync16(uint32_t sdst, const void* gsrc, int sz) {
    asm volatile("cp.async.cg.shared.global [%0], [%1], 16, %2;"
                 :: "r"(sdst), "l"(gsrc), "r"(sz));
}
#define CP_COMMIT() asm volatile("cp.async.commit_group;" ::: "memory")
#define CP_WAIT1()  asm volatile("cp.async.wait_group 1;" ::: "memory")

// ---------------- stage 1: masked_output on inputs ---------------------------
__global__ __launch_bounds__(256) void masked1_kernel(
        const float* __restrict__ in, float* __restrict__ x1o,
        float* __restrict__ posto, float* __restrict__ rawo) {
    const int b = blockIdx.x;
    const int c = blockIdx.y * 256 + threadIdx.x;
    const size_t base = (size_t)b * HW * KC + c;
    float best = -3.402823e38f; int bi = 0;
    #pragma unroll 4
    for (int p = 0; p < HW; ++p) {
        float v = in[base + (size_t)p * KC];
        if (v > best) { best = v; bi = p; }
    }
    g_arg1[b * KC + c] = bi;
    const int pi = bi / 14, pj = bi - pi * 14;
    float s = 0.f;
    #pragma unroll 2
    for (int p = 0; p < HW; ++p) {
        const int i = p / 14, j = p - i * 14;
        const float t = tpl_val(pi, pj, i, j);
        const float v = in[base + (size_t)p * KC];
        const float m = fmaxf(v * t, 0.f);
        s += m;
        x1o[base + (size_t)p * KC]   = m;
        posto[base + (size_t)p * KC] = t;
        rawo[base + (size_t)p * KC]  = v;
    }
    g_mean1[b * KC + c] = s / 196.0f;
}

// ---------------- split x1 -> bf16 hi/lo -------------------------------------
__global__ __launch_bounds__(256) void split_x1_kernel(const float* __restrict__ x1) {
    const size_t i0 = ((size_t)blockIdx.x * 256 + threadIdx.x) * 8;
    float4 v0 = *reinterpret_cast<const float4*>(x1 + i0);
    float4 v1 = *reinterpret_cast<const float4*>(x1 + i0 + 4);
    float v[8] = {v0.x, v0.y, v0.z, v0.w, v1.x, v1.y, v1.z, v1.w};
    uint32_t ph[4], pl[4];
    #pragma unroll
    for (int j = 0; j < 4; ++j) {
        __nv_bfloat162 th, tl;
        #pragma unroll
        for (int q = 0; q < 2; ++q) {
            float x = v[2*j + q];
            __nv_bfloat16 h = __float2bfloat16(x);
            __nv_bfloat16 l = __float2bfloat16(x - __bfloat162float(h));
            if (q == 0) { th.x = h; tl.x = l; } else { th.y = h; tl.y = l; }
        }
        ph[j] = *reinterpret_cast<uint32_t*>(&th);
        pl[j] = *reinterpret_cast<uint32_t*>(&tl);
    }
    *reinterpret_cast<uint4*>(g_x1h + i0) = make_uint4(ph[0], ph[1], ph[2], ph[3]);
    *reinterpret_cast<uint4*>(g_x1l + i0) = make_uint4(pl[0], pl[1], pl[2], pl[3]);
}

// ---------------- split + transpose weights (+ fp32 copy) --------------------
__global__ __launch_bounds__(512) void split_w_kernel(const float* __restrict__ w) {
    const int k  = blockIdx.x;
    const int co = threadIdx.x;
    const float v = w[(size_t)k * KC + co];
    __nv_bfloat16 h = __float2bfloat16(v);
    __nv_bfloat16 l = __float2bfloat16(v - __bfloat162float(h));
    g_wth[(size_t)co * KTOT + k] = h;
    g_wtl[(size_t)co * KTOT + k] = l;
    g_wtf[(size_t)co * KTOT + k] = v;
}

// ---------------- stage 2: conv via mma.sync bf16 3-pass split ---------------
// Block 128x128, 256 threads = 8 warps of 32x64; cp.async double-buffered.
// __launch_bounds__(256, 2) -> reg cap 128 -> 2 CTAs/SM (16 warps/SM).
#define BK2     32
#define NCH     (KTOT / BK2)      // 144
#define ASTRIDE 80
#define TILEB   (128 * ASTRIDE)
#define OFF_AH  0
#define OFF_AL  (1 * TILEB)
#define OFF_BH  (2 * TILEB)
#define OFF_BL  (3 * TILEB)
#define STAGEB  (4 * TILEB)
#define SMEMC   (2 * STAGEB)      // 81920

#define CONV_LOADC(KT, S)                                                       \
    {                                                                           \
        const int kt_ = (KT);                                                   \
        const int tap = kt_ >> 4;                                               \
        const int ci0 = (kt_ & 15) << 5;                                        \
        const int kh = tap / 3, kw = tap - kh * 3;                              \
        const int ih = oh + kh - 1, iw = ow + kw - 1;                           \
        const bool av = ((unsigned)ih < 14u) && ((unsigned)iw < 14u);           \
        const int sz = av ? 16 : 0;                                             \
        const size_t ai = av ? ((((size_t)bb * HW + ih * 14 + iw) << 9) + ci0   \
                                + lhalf * 16)                                   \
                             : 0;                                               \
        const size_t bi = bRow + ((size_t)kt_ << 5) + lhalf * 16;               \
        const uint32_t sA = smb + (S) * STAGEB + soffA;                         \
        cpasync16(sA + OFF_AH,      g_x1h + ai,     sz);                        \
        cpasync16(sA + OFF_AH + 16, g_x1h + ai + 8, sz);                        \
        cpasync16(sA + OFF_AL,      g_x1l + ai,     sz);                        \
        cpasync16(sA + OFF_AL + 16, g_x1l + ai + 8, sz);                        \
        cpasync16(sA + OFF_BH,      g_wth + bi,     16);                        \
        cpasync16(sA + OFF_BH + 16, g_wth + bi + 8, 16);                        \
        cpasync16(sA + OFF_BL,      g_wtl + bi,     16);                        \
        cpasync16(sA + OFF_BL + 16, g_wtl + bi + 8, 16);                        \
        CP_COMMIT();                                                            \
    }

__global__ __launch_bounds__(256, 2) void conv_mma_kernel(const float* __restrict__ bias) {
    extern __shared__ char sm[];
    const uint32_t smb = s2u(sm);
    const int tid = threadIdx.x, lane = tid & 31, wid = tid >> 5;
    const int n0 = blockIdx.x * 128;
    const int m0 = blockIdx.y * 128;
    const int wm = (wid >> 1) * 32;     // 4x2 warp grid, 32x64 tiles
    const int wn = (wid & 1) * 64;

    // loader geometry: thread pair covers one row of all four tiles
    const int lrow  = tid >> 1;
    const int lhalf = tid & 1;
    const int m  = m0 + lrow;
    const int bb = m / HW;
    const int pp = m - bb * HW;
    const int oh = pp / 14, ow = pp - (pp / 14) * 14;
    const size_t bRow = (size_t)(n0 + lrow) * KTOT;
    const uint32_t soffA = (uint32_t)lrow * ASTRIDE + (uint32_t)lhalf * 32;

    const uint32_t aAddr = smb + OFF_AH
        + (uint32_t)(wm + (lane & 15)) * ASTRIDE + ((uint32_t)(lane >> 4) << 4);
    const uint32_t bAddr = smb + OFF_BH
        + (uint32_t)(wn + ((lane >> 4) << 3) + (lane & 7)) * ASTRIDE
        + (((uint32_t)(lane >> 3) & 1u) << 4);

    float acc[2][8][4];
    #pragma unroll
    for (int i = 0; i < 2; ++i)
        #pragma unroll
        for (int j = 0; j < 8; ++j)
            #pragma unroll
            for (int q = 0; q < 4; ++q) acc[i][j][q] = 0.f;

    CONV_LOADC(0, 0);
    CONV_LOADC(1, 1);

    for (int kt = 0; kt < NCH; ++kt) {
        const int s = kt & 1;
        CP_WAIT1();
        __syncthreads();

        const uint32_t sbase = (uint32_t)(s * STAGEB);
        #pragma unroll
        for (int kk = 0; kk < 2; ++kk) {
            uint32_t ah[2][4], al[2][4];
            #pragma unroll
            for (int mi = 0; mi < 2; ++mi) {
                const uint32_t ra = aAddr + sbase + mi * (16 * ASTRIDE) + kk * 32;
                ldsm4(ah[mi], ra);
                ldsm4(al[mi], ra + (OFF_AL - OFF_AH));
            }
            #pragma unroll
            for (int np = 0; np < 4; ++np) {
                uint32_t bh[4], bl[4];
                const uint32_t rb = bAddr + sbase + np * (16 * ASTRIDE) + kk * 32;
                ldsm4(bh, rb);
                ldsm4(bl, rb + (OFF_BL - OFF_BH));
                #pragma unroll
                for (int mi = 0; mi < 2; ++mi) {
                    mma16816(acc[mi][2*np],   ah[mi], bh[0], bh[1]);
                    mma16816(acc[mi][2*np+1], ah[mi], bh[2], bh[3]);
                    mma16816(acc[mi][2*np],   ah[mi], bl[0], bl[1]);
                    mma16816(acc[mi][2*np+1], ah[mi], bl[2], bl[3]);
                    mma16816(acc[mi][2*np],   al[mi], bh[0], bh[1]);
                    mma16816(acc[mi][2*np+1], al[mi], bh[2], bh[3]);
                }
            }
        }

        __syncthreads();                         // all warps done reading stage s
        if (kt + 2 < NCH) CONV_LOADC(kt + 2, s); // refill stage s
    }

    // epilogue: bias + relu -> g_x3
    #pragma unroll
    for (int mi = 0; mi < 2; ++mi) {
        const int r0 = m0 + wm + mi * 16 + (lane >> 2);
        #pragma unroll
        for (int ni = 0; ni < 8; ++ni) {
            const int c = n0 + wn + ni * 8 + (lane & 3) * 2;
            const float2 bs = *reinterpret_cast<const float2*>(bias + c);
            float2 o0, o1;
            o0.x = fmaxf(acc[mi][ni][0] + bs.x, 0.f);
            o0.y = fmaxf(acc[mi][ni][1] + bs.y, 0.f);
            o1.x = fmaxf(acc[mi][ni][2] + bs.x, 0.f);
            o1.y = fmaxf(acc[mi][ni][3] + bs.y, 0.f);
            *reinterpret_cast<float2*>(g_x3 + ((size_t)r0 << 9) + c)       = o0;
            *reinterpret_cast<float2*>(g_x3 + ((size_t)(r0 + 8) << 9) + c) = o1;
        }
    }
}

// ---------------- exact fp32 conv output at one position (resolve path) ------
__device__ float exact_x3(const float* __restrict__ x1, float bias_c,
                          int b, int p, int c) {
    const int i = p / 14, j = p - (p / 14) * 14;
    const float* wrow = g_wtf + (size_t)c * KTOT;
    float s = 0.f;
    #pragma unroll 1
    for (int tap = 0; tap < 9; ++tap) {
        const int kh = tap / 3, kw = tap - kh * 3;
        const int ih = i + kh - 1, iw = j + kw - 1;
        if ((unsigned)ih < 14u && (unsigned)iw < 14u) {
            const float* xr = x1 + (((size_t)b * HW + ih * 14 + iw) << 9);
            const float* wr = wrow + tap * 512;
            #pragma unroll 8
            for (int ci = 0; ci < 512; ++ci) s = fmaf(xr[ci], wr[ci], s);
        }
    }
    return fmaxf(s + bias_c, 0.f);
}

// ---------------- stage 3: masked_output on x3 (robust argmax) ---------------
__global__ __launch_bounds__(256) void masked2_kernel(
        const float* __restrict__ x1, const float* __restrict__ cb,
        float* __restrict__ x2o) {
    const int b = blockIdx.x;
    const int c = blockIdx.y * 256 + threadIdx.x;
    const size_t base = (size_t)b * HW * KC + c;

    float best = -3.402823e38f; int bi = 0;
    #pragma unroll 4
    for (int p = 0; p < HW; ++p) {
        float v = g_x3[base + (size_t)p * KC];
        if (v > best) { best = v; bi = p; }
    }

    if (best > 0.f) {
        const float thresh = best - best * 5e-4f;
        int cand[8]; int nc = 0;
        for (int p = 0; p < HW; ++p) {
            float v = g_x3[base + (size_t)p * KC];
            if (v >= thresh) { if (nc < 8) cand[nc] = p; ++nc; }
        }
        if (nc > 1) {
            const float bias_c = cb[c];
            const int nn = nc < 8 ? nc : 8;
            float be = -3.402823e38f; int bidx = cand[0];
            for (int t = 0; t < nn; ++t) {
                const float e = exact_x3(x1, bias_c, b, cand[t], c);
                if (e > be) { be = e; bidx = cand[t]; }
            }
            bi = bidx;
        }
    }

    g_arg2[b * KC + c] = bi;
    const int pi = bi / 14, pj = bi - pi * 14;
    float s = 0.f;
    #pragma unroll 2
    for (int p = 0; p < HW; ++p) {
        const int i = p / 14, j = p - i * 14;
        const float t = tpl_val(pi, pj, i, j);
        const float v = g_x3[base + (size_t)p * KC];
        const float m = fmaxf(v * t, 0.f);
        s += m;
        x2o[base + (size_t)p * KC] = m;
    }
    g_mean2[b * KC + c] = s / 196.0f;
}

// ---------------- stage 4: per-channel class stats ---------------------------
__global__ __launch_bounds__(32) void stats_kernel(
        const int* __restrict__ gt,
        const float* __restrict__ as1, const float* __restrict__ cs1,
        const float* __restrict__ as2, const float* __restrict__ cs2) {
    __shared__ int s_gt[BATCH];
    const int tid = threadIdx.x;
    const int c = blockIdx.x * 32 + tid;
    const int layer = blockIdx.y;
    for (int i = tid; i < BATCH; i += 32) s_gt[i] = gt[i];
    __syncthreads();

    const float* mean = (layer == 0) ? g_mean1 : g_mean2;
    const float* as   = (layer == 0) ? as1 : as2;
    const float* cs   = (layer == 0) ? cs1 : cs2;

    float cnt[NCLS], act[NCLS];
    #pragma unroll
    for (int k = 0; k < NCLS; ++k) { cnt[k] = 0.f; act[k] = 0.f; }
    #pragma unroll 4
    for (int b = 0; b < BATCH; ++b) {
        const int   g = s_gt[b];
        const float v = mean[b * KC + c];
        #pragma unroll
        for (int k = 0; k < NCLS; ++k) {
            cnt[k] += (g == k) ? 1.0f : 0.0f;
            act[k] += (g == k) ? v    : 0.0f;
        }
    }
    int bestk = 0; float bestv = -3.402823e38f;
    #pragma unroll
    for (int k = 0; k < NCLS; ++k) {
        const float cn = cs[k] + cnt[k];
        const float fm = (cn == 0.f) ? 0.f : (as[c * NCLS + k] + act[k]) / cn;
        if (fm > bestv) { bestv = fm; bestk = k; }
    }
    if (layer == 0) g_fcls1[c] = bestk; else g_fcls2[c] = bestk;
}

// ---------------- stage 5: loss tensors --------------------------------------
__global__ __launch_bounds__(256) void loss_kernel(const int* __restrict__ gt,
                                                   float* __restrict__ l1,
                                                   float* __restrict__ l2) {
    const int bp = blockIdx.x;
    const int b = bp / HW;
    const int p = bp - b * HW;
    const int i = p / 14, j = p - (p / 14) * 14;
    const int c = blockIdx.y * 256 + threadIdx.x;
    const int gtb = gt[b];
    const size_t o = (size_t)bp * KC + c;

    float v1 = 0.f;
    if (g_fcls1[c] == gtb) {
        const int a = g_arg1[b * KC + c];
        const int pi = a / 14, pj = a - (a / 14) * 14;
        v1 = fmaxf(tpl_val(pi, pj, i, j), 0.f);
    }
    l1[o] = v1;

    float v2 = 0.f;
    if (g_fcls2[c] == gtb) {
        const int a = g_arg2[b * KC + c];
        const int pi = a / 14, pj = a - (a / 14) * 14;
        v2 = fmaxf(tpl_val(pi, pj, i, j), 0.f);
    }
    l2[o] = v2;
}

// ---------------- stage 6a: maxpool 2x2 + dense (partial) --------------------
__global__ __launch_bounds__(256) void dense_kernel(const float* __restrict__ x2,
                                                    const float* __restrict__ dw) {
    const int b    = blockIdx.x >> 1;
    const int half = blockIdx.x & 1;
    const int tid  = threadIdx.x;
    const float* xb = x2 + (size_t)b * HW * KC;
    float acc[NCLS];
    #pragma unroll
    for (int k = 0; k < NCLS; ++k) acc[k] = 0.f;

    const int D = 7 * 7 * KC;
    const int d0 = half * (D / 2);
    for (int d = d0 + tid; d < d0 + D / 2; d += 256) {
        const int c  = d & 511;
        const int pw = (d >> 9) % 7;
        const int ph = d / (KC * 7);
        const float* p00 = xb + ((size_t)((2 * ph) * 14 + 2 * pw)) * KC + c;
        const float m = fmaxf(fmaxf(p00[0], p00[KC]),
                              fmaxf(p00[14 * KC], p00[15 * KC]));
        const float* wr = dw + (size_t)d * NCLS;
        #pragma unroll
        for (int k = 0; k < NCLS; ++k) acc[k] = fmaf(m, wr[k], acc[k]);
    }

    __shared__ float sacc[NCLS];
    if (tid < NCLS) sacc[tid] = 0.f;
    __syncthreads();
    #pragma unroll
    for (int k = 0; k < NCLS; ++k) {
        float v = acc[k];
        for (int off = 16; off; off >>= 1) v += __shfl_down_sync(0xffffffffu, v, off);
        if ((tid & 31) == 0) atomicAdd(&sacc[k], v);
    }
    __syncthreads();
    if (tid < NCLS) g_logit[(b * 2 + half) * NCLS + tid] = sacc[tid];
}

// ---------------- stage 6b: combine + softmax --------------------------------
__global__ __launch_bounds__(32) void softmax_kernel(const float* __restrict__ db,
                                                     float* __restrict__ probs) {
    const int b = blockIdx.x;
    if (threadIdx.x == 0) {
        float lg[NCLS];
        float mx = -3.402823e38f;
        for (int k = 0; k < NCLS; ++k) {
            lg[k] = g_logit[(b * 2 + 0) * NCLS + k]
                  + g_logit[(b * 2 + 1) * NCLS + k] + db[k];
            mx = fmaxf(mx, lg[k]);
        }
        float s = 0.f;
        for (int k = 0; k < NCLS; ++k) { lg[k] = expf(lg[k] - mx); s += lg[k]; }
        for (int k = 0; k < NCLS; ++k) probs[b * NCLS + k] = lg[k] / s;
    }
}

// ---------------- launch ------------------------------------------------------
extern "C" void kernel_launch(void* const* d_in, const int* in_sizes, int n_in,
                              void* d_out, int out_size) {
    const float* inp     = (const float*)d_in[0];
    const int*   gt      = (const int*)  d_in[1];
    const float* conv_w  = (const float*)d_in[2];
    const float* conv_b  = (const float*)d_in[3];
    const float* dense_w = (const float*)d_in[4];
    const float* dense_b = (const float*)d_in[5];
    const float* as1     = (const float*)d_in[6];
    const float* as2     = (const float*)d_in[7];
    const float* cs1     = (const float*)d_in[8];
    const float* cs2     = (const float*)d_in[9];

    float* out   = (float*)d_out;
    float* probs = out;
    float* x1    = probs + BATCH * NCLS;
    float* x2    = x1 + SFEAT;
    float* loss1 = x2 + SFEAT;
    float* loss2 = loss1 + SFEAT;
    float* raw   = loss2 + SFEAT;
    float* post1 = raw + SFEAT;

    cudaFuncSetAttribute(conv_mma_kernel,
                         cudaFuncAttributeMaxDynamicSharedMemorySize, SMEMC);

    split_w_kernel<<<KTOT, 512>>>(conv_w);
    masked1_kernel<<<dim3(BATCH, 2), 256>>>(inp, x1, post1, raw);
    split_x1_kernel<<<SFEAT / 2048, 256>>>(x1);
    conv_mma_kernel<<<dim3(4, 196), 256, SMEMC>>>(conv_b);
    masked2_kernel<<<dim3(BATCH, 2), 256>>>(x1, conv_b, x2);
    stats_kernel<<<dim3(16, 2), 32>>>(gt, as1, cs1, as2, cs2);
    loss_kernel<<<dim3(BATCH * HW, 2), 256>>>(gt, loss1, loss2);
    dense_kernel<<<BATCH * 2, 256>>>(x2, dense_w);
    softmax_kernel<<<BATCH, 32>>>(dense_b, probs);
}

// round 16
// speedup vs baseline: 1.1047x; 1.0133x over previous
#include <cuda_runtime.h>
#include <cuda_bf16.h>
#include <stdint.h>
#include <math.h>

#define BATCH 128
#define HW    196
#define KC    512
#define NCLS  10
#define SFEAT (BATCH*HW*KC)   // 12845056
#define KTOT  4608            // 9 taps * 512

// ---------------- scratch (device globals; no allocation allowed) ----------
__device__ float g_x3[SFEAT];                    // relu(conv + b)
__device__ __nv_bfloat16 g_x1h[SFEAT];           // x1 split hi
__device__ __nv_bfloat16 g_x1l[SFEAT];           // x1 split lo
__device__ __nv_bfloat16 g_wth[KC*KTOT];         // W^T hi: [co][k]
__device__ __nv_bfloat16 g_wtl[KC*KTOT];         // W^T lo
__device__ float g_wtf[KC*KTOT];                 // W^T fp32 (exact resolve)
__device__ int   g_arg1[BATCH*KC];
__device__ int   g_arg2[BATCH*KC];
__device__ float g_mean1[BATCH*KC];
__device__ float g_mean2[BATCH*KC];
__device__ int   g_fcls1[KC];
__device__ int   g_fcls2[KC];
__device__ float g_logit[BATCH*2*NCLS];

__device__ __forceinline__ float tpl_val(int pi, int pj, int i, int j) {
    int di = i - pi; if (di < 0) di = -di;
    int dj = j - pj; if (dj < 0) dj = -dj;
    float v = 1.0f - (2.0f * (float)(di + dj)) / 14.0f;
    v = fmaxf(v, -1.0f);
    return (0.5f / 196.0f) * v;
}

__device__ __forceinline__ uint32_t s2u(const void* p) {
    uint32_t a;
    asm("{ .reg .u64 t; cvta.to.shared.u64 t, %1; cvt.u32.u64 %0, t; }"
        : "=r"(a) : "l"(p));
    return a;
}
__device__ __forceinline__ void ldsm4(uint32_t* r, uint32_t addr) {
    asm volatile("ldmatrix.sync.aligned.m8n8.x4.shared.b16 {%0,%1,%2,%3}, [%4];"
                 : "=r"(r[0]), "=r"(r[1]), "=r"(r[2]), "=r"(r[3]) : "r"(addr));
}
__device__ __forceinline__ void mma16816(float* d, const uint32_t* a,
                                         uint32_t b0, uint32_t b1) {
    asm volatile("mma.sync.aligned.m16n8k16.row.col.f32.bf16.bf16.f32 "
                 "{%0,%1,%2,%3}, {%4,%5,%6,%7}, {%8,%9}, {%0,%1,%2,%3};"
                 : "+f"(d[0]), "+f"(d[1]), "+f"(d[2]), "+f"(d[3])
                 : "r"(a[0]), "r"(a[1]), "r"(a[2]), "r"(a[3]), "r"(b0), "r"(b1));
}
__device__ __forceinline__ void cpasync16(uint32_t sdst, const void* gsrc, int sz) {
    asm volatile("cp.async.cg.shared.global [%0], [%1], 16, %2;"
                 :: "r"(sdst), "l"(gsrc), "r"(sz));
}
#define CP_COMMIT() asm volatile("cp.async.commit_group;" ::: "memory")
#define CP_WAIT1()  asm volatile("cp.async.wait_group 1;" ::: "memory")

// ---------------- stage 1: masked_output on inputs ---------------------------
__global__ __launch_bounds__(256) void masked1_kernel(
        const float* __restrict__ in, float* __restrict__ x1o,
        float* __restrict__ posto, float* __restrict__ rawo) {
    const int b = blockIdx.x;
    const int c = blockIdx.y * 256 + threadIdx.x;
    const size_t base = (size_t)b * HW * KC + c;
    float best = -3.402823e38f; int bi = 0;
    #pragma unroll 4
    for (int p = 0; p < HW; ++p) {
        float v = in[base + (size_t)p * KC];
        if (v > best) { best = v; bi = p; }
    }
    g_arg1[b * KC + c] = bi;
    const int pi = bi / 14, pj = bi - pi * 14;
    float s = 0.f;
    #pragma unroll 2
    for (int p = 0; p < HW; ++p) {
        const int i = p / 14, j = p - i * 14;
        const float t = tpl_val(pi, pj, i, j);
        const float v = in[base + (size_t)p * KC];
        const float m = fmaxf(v * t, 0.f);
        s += m;
        x1o[base + (size_t)p * KC]   = m;
        posto[base + (size_t)p * KC] = t;
        rawo[base + (size_t)p * KC]  = v;
    }
    g_mean1[b * KC + c] = s / 196.0f;
}

// ---------------- split x1 -> bf16 hi/lo -------------------------------------
__global__ __launch_bounds__(256) void split_x1_kernel(const float* __restrict__ x1) {
    const size_t i0 = ((size_t)blockIdx.x * 256 + threadIdx.x) * 8;
    float4 v0 = *reinterpret_cast<const float4*>(x1 + i0);
    float4 v1 = *reinterpret_cast<const float4*>(x1 + i0 + 4);
    float v[8] = {v0.x, v0.y, v0.z, v0.w, v1.x, v1.y, v1.z, v1.w};
    uint32_t ph[4], pl[4];
    #pragma unroll
    for (int j = 0; j < 4; ++j) {
        __nv_bfloat162 th, tl;
        #pragma unroll
        for (int q = 0; q < 2; ++q) {
            float x = v[2*j + q];
            __nv_bfloat16 h = __float2bfloat16(x);
            __nv_bfloat16 l = __float2bfloat16(x - __bfloat162float(h));
            if (q == 0) { th.x = h; tl.x = l; } else { th.y = h; tl.y = l; }
        }
        ph[j] = *reinterpret_cast<uint32_t*>(&th);
        pl[j] = *reinterpret_cast<uint32_t*>(&tl);
    }
    *reinterpret_cast<uint4*>(g_x1h + i0) = make_uint4(ph[0], ph[1], ph[2], ph[3]);
    *reinterpret_cast<uint4*>(g_x1l + i0) = make_uint4(pl[0], pl[1], pl[2], pl[3]);
}

// ---------------- split + transpose weights (+ fp32 copy) --------------------
__global__ __launch_bounds__(512) void split_w_kernel(const float* __restrict__ w) {
    const int k  = blockIdx.x;
    const int co = threadIdx.x;
    const float v = w[(size_t)k * KC + co];
    __nv_bfloat16 h = __float2bfloat16(v);
    __nv_bfloat16 l = __float2bfloat16(v - __bfloat162float(h));
    g_wth[(size_t)co * KTOT + k] = h;
    g_wtl[(size_t)co * KTOT + k] = l;
    g_wtf[(size_t)co * KTOT + k] = v;
}

// ---------------- stage 2: conv via mma.sync bf16 3-pass split ---------------
// Block 128x128, 256 threads = 8 warps of 32x64; cp.async double-buffered,
// B-fragment ldsm software-pipelined across np to hide LDSM latency.
#define BK2     32
#define NCH     (KTOT / BK2)      // 144
#define ASTRIDE 80
#define TILEB   (128 * ASTRIDE)
#define OFF_AH  0
#define OFF_AL  (1 * TILEB)
#define OFF_BH  (2 * TILEB)
#define OFF_BL  (3 * TILEB)
#define STAGEB  (4 * TILEB)
#define SMEMC   (2 * STAGEB)      // 81920

#define CONV_LOADC(KT, S)                                                       \
    {                                                                           \
        const int kt_ = (KT);                                                   \
        const int tap = kt_ >> 4;                                               \
        const int ci0 = (kt_ & 15) << 5;                                        \
        const int kh = tap / 3, kw = tap - kh * 3;                              \
        const int ih = oh + kh - 1, iw = ow + kw - 1;                           \
        const bool av = ((unsigned)ih < 14u) && ((unsigned)iw < 14u);           \
        const int sz = av ? 16 : 0;                                             \
        const size_t ai = av ? ((((size_t)bb * HW + ih * 14 + iw) << 9) + ci0   \
                                + lhalf * 16)                                   \
                             : 0;                                               \
        const size_t bi = bRow + ((size_t)kt_ << 5) + lhalf * 16;               \
        const uint32_t sA = smb + (S) * STAGEB + soffA;                         \
        cpasync16(sA + OFF_AH,      g_x1h + ai,     sz);                        \
        cpasync16(sA + OFF_AH + 16, g_x1h + ai + 8, sz);                        \
        cpasync16(sA + OFF_AL,      g_x1l + ai,     sz);                        \
        cpasync16(sA + OFF_AL + 16, g_x1l + ai + 8, sz);                        \
        cpasync16(sA + OFF_BH,      g_wth + bi,     16);                        \
        cpasync16(sA + OFF_BH + 16, g_wth + bi + 8, 16);                        \
        cpasync16(sA + OFF_BL,      g_wtl + bi,     16);                        \
        cpasync16(sA + OFF_BL + 16, g_wtl + bi + 8, 16);                        \
        CP_COMMIT();                                                            \
    }

__global__ __launch_bounds__(256, 2) void conv_mma_kernel(const float* __restrict__ bias) {
    extern __shared__ char sm[];
    const uint32_t smb = s2u(sm);
    const int tid = threadIdx.x, lane = tid & 31, wid = tid >> 5;
    const int n0 = blockIdx.x * 128;
    const int m0 = blockIdx.y * 128;
    const int wm = (wid >> 1) * 32;     // 4x2 warp grid, 32x64 tiles
    const int wn = (wid & 1) * 64;

    // loader geometry: thread pair covers one row of all four tiles
    const int lrow  = tid >> 1;
    const int lhalf = tid & 1;
    const int m  = m0 + lrow;
    const int bb = m / HW;
    const int pp = m - bb * HW;
    const int oh = pp / 14, ow = pp - (pp / 14) * 14;
    const size_t bRow = (size_t)(n0 + lrow) * KTOT;
    const uint32_t soffA = (uint32_t)lrow * ASTRIDE + (uint32_t)lhalf * 32;

    const uint32_t aAddr = smb + OFF_AH
        + (uint32_t)(wm + (lane & 15)) * ASTRIDE + ((uint32_t)(lane >> 4) << 4);
    const uint32_t bAddr = smb + OFF_BH
        + (uint32_t)(wn + ((lane >> 4) << 3) + (lane & 7)) * ASTRIDE
        + (((uint32_t)(lane >> 3) & 1u) << 4);

    float acc[2][8][4];
    #pragma unroll
    for (int i = 0; i < 2; ++i)
        #pragma unroll
        for (int j = 0; j < 8; ++j)
            #pragma unroll
            for (int q = 0; q < 4; ++q) acc[i][j][q] = 0.f;

    CONV_LOADC(0, 0);
    CONV_LOADC(1, 1);

    for (int kt = 0; kt < NCH; ++kt) {
        const int s = kt & 1;
        CP_WAIT1();
        __syncthreads();

        const uint32_t sbase = (uint32_t)(s * STAGEB);
        #pragma unroll
        for (int kk = 0; kk < 2; ++kk) {
            // A fragments for this k-slice
            uint32_t ah[2][4], al[2][4];
            #pragma unroll
            for (int mi = 0; mi < 2; ++mi) {
                const uint32_t ra = aAddr + sbase + mi * (16 * ASTRIDE) + kk * 32;
                ldsm4(ah[mi], ra);
                ldsm4(al[mi], ra + (OFF_AL - OFF_AH));
            }
            // B fragments double-buffered across np: prefetch np+1 while
            // computing np, so LDSM latency hides under 12 mmas of work.
            uint32_t bh[2][4], bl[2][4];
            {
                const uint32_t rb0 = bAddr + sbase + kk * 32;
                ldsm4(bh[0], rb0);
                ldsm4(bl[0], rb0 + (OFF_BL - OFF_BH));
            }
            #pragma unroll
            for (int np = 0; np < 4; ++np) {
                const int cb = np & 1, nb = cb ^ 1;
                if (np < 3) {
                    const uint32_t rb = bAddr + sbase
                        + (np + 1) * (16 * ASTRIDE) + kk * 32;
                    ldsm4(bh[nb], rb);
                    ldsm4(bl[nb], rb + (OFF_BL - OFF_BH));
                }
                // pass-major across mi: accumulator RAW distance = 4 mmas
                mma16816(acc[0][2*np],   ah[0], bh[cb][0], bh[cb][1]);
                mma16816(acc[0][2*np+1], ah[0], bh[cb][2], bh[cb][3]);
                mma16816(acc[1][2*np],   ah[1], bh[cb][0], bh[cb][1]);
                mma16816(acc[1][2*np+1], ah[1], bh[cb][2], bh[cb][3]);
                mma16816(acc[0][2*np],   ah[0], bl[cb][0], bl[cb][1]);
                mma16816(acc[0][2*np+1], ah[0], bl[cb][2], bl[cb][3]);
                mma16816(acc[1][2*np],   ah[1], bl[cb][0], bl[cb][1]);
                mma16816(acc[1][2*np+1], ah[1], bl[cb][2], bl[cb][3]);
                mma16816(acc[0][2*np],   al[0], bh[cb][0], bh[cb][1]);
                mma16816(acc[0][2*np+1], al[0], bh[cb][2], bh[cb][3]);
                mma16816(acc[1][2*np],   al[1], bh[cb][0], bh[cb][1]);
                mma16816(acc[1][2*np+1], al[1], bh[cb][2], bh[cb][3]);
            }
        }

        __syncthreads();                         // all warps done reading stage s
        if (kt + 2 < NCH) CONV_LOADC(kt + 2, s); // refill stage s
    }

    // epilogue: bias + relu -> g_x3
    #pragma unroll
    for (int mi = 0; mi < 2; ++mi) {
        const int r0 = m0 + wm + mi * 16 + (lane >> 2);
        #pragma unroll
        for (int ni = 0; ni < 8; ++ni) {
            const int c = n0 + wn + ni * 8 + (lane & 3) * 2;
            const float2 bs = *reinterpret_cast<const float2*>(bias + c);
            float2 o0, o1;
            o0.x = fmaxf(acc[mi][ni][0] + bs.x, 0.f);
            o0.y = fmaxf(acc[mi][ni][1] + bs.y, 0.f);
            o1.x = fmaxf(acc[mi][ni][2] + bs.x, 0.f);
            o1.y = fmaxf(acc[mi][ni][3] + bs.y, 0.f);
            *reinterpret_cast<float2*>(g_x3 + ((size_t)r0 << 9) + c)       = o0;
            *reinterpret_cast<float2*>(g_x3 + ((size_t)(r0 + 8) << 9) + c) = o1;
        }
    }
}

// ---------------- exact fp32 conv output at one position (resolve path) ------
__device__ float exact_x3(const float* __restrict__ x1, float bias_c,
                          int b, int p, int c) {
    const int i = p / 14, j = p - (p / 14) * 14;
    const float* wrow = g_wtf + (size_t)c * KTOT;
    float s = 0.f;
    #pragma unroll 1
    for (int tap = 0; tap < 9; ++tap) {
        const int kh = tap / 3, kw = tap - kh * 3;
        const int ih = i + kh - 1, iw = j + kw - 1;
        if ((unsigned)ih < 14u && (unsigned)iw < 14u) {
            const float* xr = x1 + (((size_t)b * HW + ih * 14 + iw) << 9);
            const float* wr = wrow + tap * 512;
            #pragma unroll 8
            for (int ci = 0; ci < 512; ++ci) s = fmaf(xr[ci], wr[ci], s);
        }
    }
    return fmaxf(s + bias_c, 0.f);
}

// ---------------- stage 3: masked_output on x3 (robust argmax) ---------------
__global__ __launch_bounds__(256) void masked2_kernel(
        const float* __restrict__ x1, const float* __restrict__ cb,
        float* __restrict__ x2o) {
    const int b = blockIdx.x;
    const int c = blockIdx.y * 256 + threadIdx.x;
    const size_t base = (size_t)b * HW * KC + c;

    float best = -3.402823e38f; int bi = 0;
    #pragma unroll 4
    for (int p = 0; p < HW; ++p) {
        float v = g_x3[base + (size_t)p * KC];
        if (v > best) { best = v; bi = p; }
    }

    if (best > 0.f) {
        const float thresh = best - best * 5e-4f;
        int cand[8]; int nc = 0;
        for (int p = 0; p < HW; ++p) {
            float v = g_x3[base + (size_t)p * KC];
            if (v >= thresh) { if (nc < 8) cand[nc] = p; ++nc; }
        }
        if (nc > 1) {
            const float bias_c = cb[c];
            const int nn = nc < 8 ? nc : 8;
            float be = -3.402823e38f; int bidx = cand[0];
            for (int t = 0; t < nn; ++t) {
                const float e = exact_x3(x1, bias_c, b, cand[t], c);
                if (e > be) { be = e; bidx = cand[t]; }
            }
            bi = bidx;
        }
    }

    g_arg2[b * KC + c] = bi;
    const int pi = bi / 14, pj = bi - pi * 14;
    float s = 0.f;
    #pragma unroll 2
    for (int p = 0; p < HW; ++p) {
        const int i = p / 14, j = p - i * 14;
        const float t = tpl_val(pi, pj, i, j);
        const float v = g_x3[base + (size_t)p * KC];
        const float m = fmaxf(v * t, 0.f);
        s += m;
        x2o[base + (size_t)p * KC] = m;
    }
    g_mean2[b * KC + c] = s / 196.0f;
}

// ---------------- stage 4: per-channel class stats ---------------------------
__global__ __launch_bounds__(32) void stats_kernel(
        const int* __restrict__ gt,
        const float* __restrict__ as1, const float* __restrict__ cs1,
        const float* __restrict__ as2, const float* __restrict__ cs2) {
    __shared__ int s_gt[BATCH];
    const int tid = threadIdx.x;
    const int c = blockIdx.x * 32 + tid;
    const int layer = blockIdx.y;
    for (int i = tid; i < BATCH; i += 32) s_gt[i] = gt[i];
    __syncthreads();

    const float* mean = (layer == 0) ? g_mean1 : g_mean2;
    const float* as   = (layer == 0) ? as1 : as2;
    const float* cs   = (layer == 0) ? cs1 : cs2;

    float cnt[NCLS], act[NCLS];
    #pragma unroll
    for (int k = 0; k < NCLS; ++k) { cnt[k] = 0.f; act[k] = 0.f; }
    #pragma unroll 4
    for (int b = 0; b < BATCH; ++b) {
        const int   g = s_gt[b];
        const float v = mean[b * KC + c];
        #pragma unroll
        for (int k = 0; k < NCLS; ++k) {
            cnt[k] += (g == k) ? 1.0f : 0.0f;
            act[k] += (g == k) ? v    : 0.0f;
        }
    }
    int bestk = 0; float bestv = -3.402823e38f;
    #pragma unroll
    for (int k = 0; k < NCLS; ++k) {
        const float cn = cs[k] + cnt[k];
        const float fm = (cn == 0.f) ? 0.f : (as[c * NCLS + k] + act[k]) / cn;
        if (fm > bestv) { bestv = fm; bestk = k; }
    }
    if (layer == 0) g_fcls1[c] = bestk; else g_fcls2[c] = bestk;
}

// ---------------- stage 5: loss tensors --------------------------------------
__global__ __launch_bounds__(256) void loss_kernel(const int* __restrict__ gt,
                                                   float* __restrict__ l1,
                                                   float* __restrict__ l2) {
    const int bp = blockIdx.x;
    const int b = bp / HW;
    const int p = bp - b * HW;
    const int i = p / 14, j = p - (p / 14) * 14;
    const int c = blockIdx.y * 256 + threadIdx.x;
    const int gtb = gt[b];
    const size_t o = (size_t)bp * KC + c;

    float v1 = 0.f;
    if (g_fcls1[c] == gtb) {
        const int a = g_arg1[b * KC + c];
        const int pi = a / 14, pj = a - (a / 14) * 14;
        v1 = fmaxf(tpl_val(pi, pj, i, j), 0.f);
    }
    l1[o] = v1;

    float v2 = 0.f;
    if (g_fcls2[c] == gtb) {
        const int a = g_arg2[b * KC + c];
        const int pi = a / 14, pj = a - (a / 14) * 14;
        v2 = fmaxf(tpl_val(pi, pj, i, j), 0.f);
    }
    l2[o] = v2;
}

// ---------------- stage 6a: maxpool 2x2 + dense (partial) --------------------
__global__ __launch_bounds__(256) void dense_kernel(const float* __restrict__ x2,
                                                    const float* __restrict__ dw) {
    const int b    = blockIdx.x >> 1;
    const int half = blockIdx.x & 1;
    const int tid  = threadIdx.x;
    const float* xb = x2 + (size_t)b * HW * KC;
    float acc[NCLS];
    #pragma unroll
    for (int k = 0; k < NCLS; ++k) acc[k] = 0.f;

    const int D = 7 * 7 * KC;
    const int d0 = half * (D / 2);
    for (int d = d0 + tid; d < d0 + D / 2; d += 256) {
        const int c  = d & 511;
        const int pw = (d >> 9) % 7;
        const int ph = d / (KC * 7);
        const float* p00 = xb + ((size_t)((2 * ph) * 14 + 2 * pw)) * KC + c;
        const float m = fmaxf(fmaxf(p00[0], p00[KC]),
                              fmaxf(p00[14 * KC], p00[15 * KC]));
        const float* wr = dw + (size_t)d * NCLS;
        #pragma unroll
        for (int k = 0; k < NCLS; ++k) acc[k] = fmaf(m, wr[k], acc[k]);
    }

    __shared__ float sacc[NCLS];
    if (tid < NCLS) sacc[tid] = 0.f;
    __syncthreads();
    #pragma unroll
    for (int k = 0; k < NCLS; ++k) {
        float v = acc[k];
        for (int off = 16; off; off >>= 1) v += __shfl_down_sync(0xffffffffu, v, off);
        if ((tid & 31) == 0) atomicAdd(&sacc[k], v);
    }
    __syncthreads();
    if (tid < NCLS) g_logit[(b * 2 + half) * NCLS + tid] = sacc[tid];
}

// ---------------- stage 6b: combine + softmax --------------------------------
__global__ __launch_bounds__(32) void softmax_kernel(const float* __restrict__ db,
                                                     float* __restrict__ probs) {
    const int b = blockIdx.x;
    if (threadIdx.x == 0) {
        float lg[NCLS];
        float mx = -3.402823e38f;
        for (int k = 0; k < NCLS; ++k) {
            lg[k] = g_logit[(b * 2 + 0) * NCLS + k]
                  + g_logit[(b * 2 + 1) * NCLS + k] + db[k];
            mx = fmaxf(mx, lg[k]);
        }
        float s = 0.f;
        for (int k = 0; k < NCLS; ++k) { lg[k] = expf(lg[k] - mx); s += lg[k]; }
        for (int k = 0; k < NCLS; ++k) probs[b * NCLS + k] = lg[k] / s;
    }
}

// ---------------- launch ------------------------------------------------------
extern "C" void kernel_launch(void* const* d_in, const int* in_sizes, int n_in,
                              void* d_out, int out_size) {
    const float* inp     = (const float*)d_in[0];
    const int*   gt      = (const int*)  d_in[1];
    const float* conv_w  = (const float*)d_in[2];
    const float* conv_b  = (const float*)d_in[3];
    const float* dense_w = (const float*)d_in[4];
    const float* dense_b = (const float*)d_in[5];
    const float* as1     = (const float*)d_in[6];
    const float* as2     = (const float*)d_in[7];
    const float* cs1     = (const float*)d_in[8];
    const float* cs2     = (const float*)d_in[9];

    float* out   = (float*)d_out;
    float* probs = out;
    float* x1    = probs + BATCH * NCLS;
    float* x2    = x1 + SFEAT;
    float* loss1 = x2 + SFEAT;
    float* loss2 = loss1 + SFEAT;
    float* raw   = loss2 + SFEAT;
    float* post1 = raw + SFEAT;

    cudaFuncSetAttribute(conv_mma_kernel,
                         cudaFuncAttributeMaxDynamicSharedMemorySize, SMEMC);

    split_w_kernel<<<KTOT, 512>>>(conv_w);
    masked1_kernel<<<dim3(BATCH, 2), 256>>>(inp, x1, post1, raw);
    split_x1_kernel<<<SFEAT / 2048, 256>>>(x1);
    conv_mma_kernel<<<dim3(4, 196), 256, SMEMC>>>(conv_b);
    masked2_kernel<<<dim3(BATCH, 2), 256>>>(x1, conv_b, x2);
    stats_kernel<<<dim3(16, 2), 32>>>(gt, as1, cs1, as2, cs2);
    loss_kernel<<<dim3(BATCH * HW, 2), 256>>>(gt, loss1, loss2);
    dense_kernel<<<BATCH * 2, 256>>>(x2, dense_w);
    softmax_kernel<<<BATCH, 32>>>(dense_b, probs);
}